// round 13
// baseline (speedup 1.0000x reference)
#include <cuda_runtime.h>
#include <cstdint>

// Shapes (compile-time constants for this problem)
#define NB 8
#define CI 256
#define HH 64
#define WW 64
#define OC 256
#define KK 9
#define OH 64
#define OW 64
#define MTOT (NB * OH * OW)      // 32768
#define KC   (KK * CI)           // 2304

// Scratch (static device globals: allocation-free)
__device__ float g_xT[(size_t)NB * HH * WW * CI];        // channel-last x: [n][y][x][c]
__device__ float g_cols[(size_t)MTOT * KC];              // im2col [m][kc] (tf32-rounded)
__device__ float g_wt[(size_t)KC * OC];                  // transposed weight [kc][o] (tf32-rounded)

// ---------------------------------------------------------------------------
// Kernel 1: NCHW -> channel-last transpose of x
// ---------------------------------------------------------------------------
__global__ void transpose_x_kernel(const float* __restrict__ x) {
    __shared__ float tile[32][33];
    const int n  = blockIdx.z;
    const int p0 = blockIdx.x * 32;
    const int c0 = blockIdx.y * 32;
    const int tx = threadIdx.x, ty = threadIdx.y;
#pragma unroll
    for (int j = 0; j < 4; j++) {
        int c = c0 + ty + j * 8;
        tile[ty + j * 8][tx] = x[((size_t)(n * CI + c) << 12) + p0 + tx];
    }
    __syncthreads();
#pragma unroll
    for (int j = 0; j < 4; j++) {
        int p = p0 + ty + j * 8;
        g_xT[((size_t)n << 20) + ((size_t)p << 8) + c0 + tx] = tile[tx][ty + j * 8];
    }
}

// ---------------------------------------------------------------------------
// Kernel 2: weight transpose + tf32 rounding
// ---------------------------------------------------------------------------
__global__ void wt_kernel(const float* __restrict__ w) {
    const int kc = blockIdx.x;
    const int o  = threadIdx.x;
    const int k  = kc >> 8;
    const int c  = kc & 255;
    float v = w[(size_t)o * KC + c * KK + k];
    uint32_t u;
    asm("cvt.rna.tf32.f32 %0, %1;" : "=r"(u) : "f"(v));
    g_wt[(size_t)kc * OC + o] = __uint_as_float(u);
}

// ---------------------------------------------------------------------------
// Kernel 3: bilinear gather / im2col, float4-vectorized, .cs stores.
// LOCALITY BLOCKING: one block = 2 consecutive m (same spatial neighborhood)
// x 9 taps = 18 warps. All corner-row reads of the ~4x5 pixel neighborhood
// run concurrently on one SM -> L1 catches the ~3x row reuse across taps,
// cutting L2 read traffic ~3x (gather is L2-read bound).
// ---------------------------------------------------------------------------
__global__ __launch_bounds__(576) void gather_kernel(const float* __restrict__ offset) {
    const int wid  = threadIdx.x >> 5;        // 0..17
    const int lane = threadIdx.x & 31;
    const int k = wid % KK;
    const int m = blockIdx.x * 2 + wid / KK;
    const int n  = m >> 12;
    const int p  = m & 4095;
    const int oh = p >> 6;
    const int ow = p & 63;

    const float offy = offset[((size_t)(n * 18 + 2 * k) << 12) + p];
    const float offx = offset[((size_t)(n * 18 + 2 * k + 1) << 12) + p];

    const float yf = (float)(k / 3 - 1 + oh) + offy;
    const float xf = (float)(k % 3 - 1 + ow) + offx;
    const float y0f = floorf(yf), x0f = floorf(xf);
    const int y0 = (int)y0f, x0 = (int)x0f;
    const int y1 = y0 + 1,   x1 = x0 + 1;
    const float fy = yf - y0f, fx = xf - x0f;
    const float gy = 1.0f - fy, gx = 1.0f - fx;

    const bool vy0 = (y0 >= 0) & (y0 < HH);
    const bool vy1 = (y1 >= 0) & (y1 < HH);
    const bool vx0 = (x0 >= 0) & (x0 < WW);
    const bool vx1 = (x1 >= 0) & (x1 < WW);

    const float w00 = gy * gx * ((vy0 & vx0) ? 1.0f : 0.0f);
    const float w01 = gy * fx * ((vy0 & vx1) ? 1.0f : 0.0f);
    const float w10 = fy * gx * ((vy1 & vx0) ? 1.0f : 0.0f);
    const float w11 = fy * fx * ((vy1 & vx1) ? 1.0f : 0.0f);

    const int y0c = min(max(y0, 0), HH - 1), y1c = min(max(y1, 0), HH - 1);
    const int x0c = min(max(x0, 0), WW - 1), x1c = min(max(x1, 0), WW - 1);

    const float* xb  = g_xT + ((size_t)n << 20);
    const float* p00 = xb + (((y0c << 6) + x0c) << 8);
    const float* p01 = xb + (((y0c << 6) + x1c) << 8);
    const float* p10 = xb + (((y1c << 6) + x0c) << 8);
    const float* p11 = xb + (((y1c << 6) + x1c) << 8);

    float* cp = g_cols + (size_t)m * KC + (k << 8);

#pragma unroll
    for (int j = 0; j < 2; j++) {
        const int c = j * 128 + lane * 4;
        float4 a = *(const float4*)(p00 + c);
        float4 b = *(const float4*)(p01 + c);
        float4 d = *(const float4*)(p10 + c);
        float4 e = *(const float4*)(p11 + c);
        float4 r;
        r.x = w00 * a.x + w01 * b.x + w10 * d.x + w11 * e.x;
        r.y = w00 * a.y + w01 * b.y + w10 * d.y + w11 * e.y;
        r.z = w00 * a.z + w01 * b.z + w10 * d.z + w11 * e.z;
        r.w = w00 * a.w + w01 * b.w + w10 * d.w + w11 * e.w;
        uint32_t u0, u1, u2, u3;
        asm("cvt.rna.tf32.f32 %0, %1;" : "=r"(u0) : "f"(r.x));
        asm("cvt.rna.tf32.f32 %0, %1;" : "=r"(u1) : "f"(r.y));
        asm("cvt.rna.tf32.f32 %0, %1;" : "=r"(u2) : "f"(r.z));
        asm("cvt.rna.tf32.f32 %0, %1;" : "=r"(u3) : "f"(r.w));
        r.x = __uint_as_float(u0); r.y = __uint_as_float(u1);
        r.z = __uint_as_float(u2); r.w = __uint_as_float(u3);
        __stcs((float4*)(cp + c), r);
    }
}

// ---------------------------------------------------------------------------
// Kernel 4: tf32 GEMM — EXACT R8 configuration (measured 215us, passed twice).
// 128x128 CTA tile, 4 warps (2x2), 64x64 warp tiles, cp.async 4-stage
// pipeline, K-step 8, mma.m16n8k8.tf32. Grid (OC/128, MTOT/128), bx fastest
// so the two CTAs sharing an A-panel are adjacent bids -> A re-read hits L2.
// ---------------------------------------------------------------------------
#define CP_ASYNC16(dst, src) \
    asm volatile("cp.async.cg.shared.global [%0], [%1], 16;\n" :: \
                 "r"((unsigned)__cvta_generic_to_shared(dst)), "l"(src))
#define CP_COMMIT() asm volatile("cp.async.commit_group;\n")
#define CP_WAIT2()  asm volatile("cp.async.wait_group 2;\n")

#define NKT (KC / 8)   // 288

__global__ __launch_bounds__(128, 2) void gemm_kernel(float* __restrict__ out) {
    __shared__ float As[4][128][12];   // [stage][m][k], pad 12: conflict-free A frags
    __shared__ float Bs[4][8][136];    // [stage][k][n], pad 136: conflict-free B frags

    const int t    = threadIdx.x;      // 0..127
    const int lane = t & 31, wid = t >> 5;
    const int warpM = wid >> 1, warpN = wid & 1;   // 2 x 2
    const int qid = lane >> 2, kq = lane & 3;
    const int bm = blockIdx.y * 128, bnn = blockIdx.x * 128;   // bx fastest = bn

    float acc[4][8][4];
#pragma unroll
    for (int a = 0; a < 4; a++)
#pragma unroll
        for (int b = 0; b < 8; b++)
#pragma unroll
            for (int c = 0; c < 4; c++) acc[a][b][c] = 0.0f;

    // staging indices: 2 A-chunks + 2 B-chunks of 16B per thread per stage
    const int am0 = t >> 1, aseg = (t & 1) * 4;
    const int am1 = (t + 128) >> 1;
    const int aseg1 = ((t + 128) & 1) * 4;
    const int bk0 = t >> 5, bn0 = (t & 31) * 4;
    const int bk1 = (t + 128) >> 5, bn1 = bn0;

    // prologue: issue stages 0,1,2
#pragma unroll
    for (int s = 0; s < 3; s++) {
        CP_ASYNC16(&As[s][am0][aseg],  g_cols + (size_t)(bm + am0) * KC + s * 8 + aseg);
        CP_ASYNC16(&As[s][am1][aseg1], g_cols + (size_t)(bm + am1) * KC + s * 8 + aseg1);
        CP_ASYNC16(&Bs[s][bk0][bn0],   g_wt + (size_t)(s * 8 + bk0) * OC + bnn + bn0);
        CP_ASYNC16(&Bs[s][bk1][bn1],   g_wt + (size_t)(s * 8 + bk1) * OC + bnn + bn1);
        CP_COMMIT();
    }

    for (int kt = 0; kt < NKT; ++kt) {
        CP_WAIT2();            // stage kt complete
        __syncthreads();       // all warps done with stage kt-1 compute; data visible

        // issue stage kt+3 into slot (kt+3)&3 (clamped at tail; redundant loads harmless)
        {
            const int ks = (kt + 3 < NKT) ? (kt + 3) : (NKT - 1);
            const int sl = (kt + 3) & 3;
            CP_ASYNC16(&As[sl][am0][aseg],  g_cols + (size_t)(bm + am0) * KC + ks * 8 + aseg);
            CP_ASYNC16(&As[sl][am1][aseg1], g_cols + (size_t)(bm + am1) * KC + ks * 8 + aseg1);
            CP_ASYNC16(&Bs[sl][bk0][bn0],   g_wt + (size_t)(ks * 8 + bk0) * OC + bnn + bn0);
            CP_ASYNC16(&Bs[sl][bk1][bn1],   g_wt + (size_t)(ks * 8 + bk1) * OC + bnn + bn1);
            CP_COMMIT();
        }

        const int cur = kt & 3;

        // B fragments: 8 n-subtiles of 8
        uint32_t bf[8][2];
#pragma unroll
        for (int ni = 0; ni < 8; ni++) {
            const int nb = warpN * 64 + ni * 8 + qid;
            bf[ni][0] = __float_as_uint(Bs[cur][kq][nb]);
            bf[ni][1] = __float_as_uint(Bs[cur][kq + 4][nb]);
        }
#pragma unroll
        for (int mi = 0; mi < 4; mi++) {
            const int mb = warpM * 64 + mi * 16 + qid;
            uint32_t a0 = __float_as_uint(As[cur][mb][kq]);
            uint32_t a1 = __float_as_uint(As[cur][mb + 8][kq]);
            uint32_t a2 = __float_as_uint(As[cur][mb][kq + 4]);
            uint32_t a3 = __float_as_uint(As[cur][mb + 8][kq + 4]);
#pragma unroll
            for (int ni = 0; ni < 8; ni++) {
                asm volatile(
                    "mma.sync.aligned.m16n8k8.row.col.f32.tf32.tf32.f32 "
                    "{%0,%1,%2,%3},{%4,%5,%6,%7},{%8,%9},{%0,%1,%2,%3};\n"
                    : "+f"(acc[mi][ni][0]), "+f"(acc[mi][ni][1]),
                      "+f"(acc[mi][ni][2]), "+f"(acc[mi][ni][3])
                    : "r"(a0), "r"(a1), "r"(a2), "r"(a3),
                      "r"(bf[ni][0]), "r"(bf[ni][1]));
            }
        }
    }

    // epilogue: out[n][o][oh][ow]; m = n*4096 + p
#pragma unroll
    for (int mi = 0; mi < 4; mi++) {
#pragma unroll
        for (int h = 0; h < 2; h++) {
            const int m = bm + warpM * 64 + mi * 16 + qid + h * 8;
            const int nimg = m >> 12;
            const size_t base = ((size_t)nimg << 20) + (m & 4095);
#pragma unroll
            for (int ni = 0; ni < 8; ni++) {
                const int o = bnn + warpN * 64 + ni * 8 + kq * 2;
                out[base + (size_t)o * 4096]       = acc[mi][ni][h * 2 + 0];
                out[base + (size_t)(o + 1) * 4096] = acc[mi][ni][h * 2 + 1];
            }
        }
    }
}

// ---------------------------------------------------------------------------
extern "C" void kernel_launch(void* const* d_in, const int* in_sizes, int n_in,
                              void* d_out, int out_size) {
    const float* x      = (const float*)d_in[0];
    const float* offset = (const float*)d_in[1];
    const float* weight = (const float*)d_in[2];
    float* out = (float*)d_out;

    transpose_x_kernel<<<dim3(128, 8, 8), dim3(32, 8)>>>(x);
    wt_kernel<<<KC, 256>>>(weight);
    gather_kernel<<<MTOT / 2, 576>>>(offset);
    gemm_kernel<<<dim3(OC / 128, MTOT / 128), 128>>>(out);
}

// round 14
// speedup vs baseline: 1.5781x; 1.5781x over previous
#include <cuda_runtime.h>
#include <cstdint>

// Shapes (compile-time constants for this problem)
#define NB 8
#define CI 256
#define HH 64
#define WW 64
#define OC 256
#define KK 9
#define OH 64
#define OW 64
#define MTOT (NB * OH * OW)      // 32768
#define KC   (KK * CI)           // 2304

// Scratch (static device globals: allocation-free)
__device__ float g_xT[(size_t)NB * HH * WW * CI];        // channel-last x: [n][y][x][c]
__device__ float g_cols[(size_t)MTOT * KC];              // im2col [m][kc] (tf32-rounded)
__device__ float g_wt[(size_t)KC * OC];                  // transposed weight [kc][o] (tf32-rounded)

// ---------------------------------------------------------------------------
// Kernel 1: NCHW -> channel-last transpose of x
// ---------------------------------------------------------------------------
__global__ void transpose_x_kernel(const float* __restrict__ x) {
    __shared__ float tile[32][33];
    const int n  = blockIdx.z;
    const int p0 = blockIdx.x * 32;
    const int c0 = blockIdx.y * 32;
    const int tx = threadIdx.x, ty = threadIdx.y;
#pragma unroll
    for (int j = 0; j < 4; j++) {
        int c = c0 + ty + j * 8;
        tile[ty + j * 8][tx] = x[((size_t)(n * CI + c) << 12) + p0 + tx];
    }
    __syncthreads();
#pragma unroll
    for (int j = 0; j < 4; j++) {
        int p = p0 + ty + j * 8;
        g_xT[((size_t)n << 20) + ((size_t)p << 8) + c0 + tx] = tile[tx][ty + j * 8];
    }
}

// ---------------------------------------------------------------------------
// Kernel 2: weight transpose + tf32 rounding
// ---------------------------------------------------------------------------
__global__ void wt_kernel(const float* __restrict__ w) {
    const int kc = blockIdx.x;
    const int o  = threadIdx.x;
    const int k  = kc >> 8;
    const int c  = kc & 255;
    float v = w[(size_t)o * KC + c * KK + k];
    uint32_t u;
    asm("cvt.rna.tf32.f32 %0, %1;" : "=r"(u) : "f"(v));
    g_wt[(size_t)kc * OC + o] = __uint_as_float(u);
}

// ---------------------------------------------------------------------------
// Kernel 3: bilinear gather / im2col (exact R8 version: one warp per (m,k),
// float4-vectorized, .cs stores; measured good twice)
// ---------------------------------------------------------------------------
__global__ __launch_bounds__(256) void gather_kernel(const float* __restrict__ offset) {
    const int gw   = blockIdx.x * 8 + (threadIdx.x >> 5);
    const int lane = threadIdx.x & 31;
    const int k = gw % KK;
    const int m = gw / KK;
    const int n  = m >> 12;
    const int p  = m & 4095;
    const int oh = p >> 6;
    const int ow = p & 63;

    const float offy = offset[((size_t)(n * 18 + 2 * k) << 12) + p];
    const float offx = offset[((size_t)(n * 18 + 2 * k + 1) << 12) + p];

    const float yf = (float)(k / 3 - 1 + oh) + offy;
    const float xf = (float)(k % 3 - 1 + ow) + offx;
    const float y0f = floorf(yf), x0f = floorf(xf);
    const int y0 = (int)y0f, x0 = (int)x0f;
    const int y1 = y0 + 1,   x1 = x0 + 1;
    const float fy = yf - y0f, fx = xf - x0f;
    const float gy = 1.0f - fy, gx = 1.0f - fx;

    const bool vy0 = (y0 >= 0) & (y0 < HH);
    const bool vy1 = (y1 >= 0) & (y1 < HH);
    const bool vx0 = (x0 >= 0) & (x0 < WW);
    const bool vx1 = (x1 >= 0) & (x1 < WW);

    const float w00 = gy * gx * ((vy0 & vx0) ? 1.0f : 0.0f);
    const float w01 = gy * fx * ((vy0 & vx1) ? 1.0f : 0.0f);
    const float w10 = fy * gx * ((vy1 & vx0) ? 1.0f : 0.0f);
    const float w11 = fy * fx * ((vy1 & vx1) ? 1.0f : 0.0f);

    const int y0c = min(max(y0, 0), HH - 1), y1c = min(max(y1, 0), HH - 1);
    const int x0c = min(max(x0, 0), WW - 1), x1c = min(max(x1, 0), WW - 1);

    const float* xb  = g_xT + ((size_t)n << 20);
    const float* p00 = xb + (((y0c << 6) + x0c) << 8);
    const float* p01 = xb + (((y0c << 6) + x1c) << 8);
    const float* p10 = xb + (((y1c << 6) + x0c) << 8);
    const float* p11 = xb + (((y1c << 6) + x1c) << 8);

    float* cp = g_cols + (size_t)m * KC + (k << 8);

#pragma unroll
    for (int j = 0; j < 2; j++) {
        const int c = j * 128 + lane * 4;
        float4 a = *(const float4*)(p00 + c);
        float4 b = *(const float4*)(p01 + c);
        float4 d = *(const float4*)(p10 + c);
        float4 e = *(const float4*)(p11 + c);
        float4 r;
        r.x = w00 * a.x + w01 * b.x + w10 * d.x + w11 * e.x;
        r.y = w00 * a.y + w01 * b.y + w10 * d.y + w11 * e.y;
        r.z = w00 * a.z + w01 * b.z + w10 * d.z + w11 * e.z;
        r.w = w00 * a.w + w01 * b.w + w10 * d.w + w11 * e.w;
        uint32_t u0, u1, u2, u3;
        asm("cvt.rna.tf32.f32 %0, %1;" : "=r"(u0) : "f"(r.x));
        asm("cvt.rna.tf32.f32 %0, %1;" : "=r"(u1) : "f"(r.y));
        asm("cvt.rna.tf32.f32 %0, %1;" : "=r"(u2) : "f"(r.z));
        asm("cvt.rna.tf32.f32 %0, %1;" : "=r"(u3) : "f"(r.w));
        r.x = __uint_as_float(u0); r.y = __uint_as_float(u1);
        r.z = __uint_as_float(u2); r.w = __uint_as_float(u3);
        __stcs((float4*)(cp + c), r);
    }
}

// ---------------------------------------------------------------------------
// Kernel 4: tf32 GEMM — R8 structure with pipeline depth 5 (was 4).
// 128x128 CTA tile, 4 warps (2x2), 64x64 warp tiles, K-step 8,
// mma.m16n8k8.tf32. Prologue commits stages 0..3; iteration kt: wait_group 3
// => completed through group (4+kt-1)-3 = kt => stage kt resident; issue
// stage kt+4 into slot (kt+4)%5 whose last reads were iter kt-1's fragment
// loads, sealed by this iteration's barrier. ~1120 cyc cp.async slack now
// covers DRAM latency (577) with margin. Dynamic smem 52.5KB, 2 CTAs/SM.
// ---------------------------------------------------------------------------
#define CP_ASYNC16(dst, src) \
    asm volatile("cp.async.cg.shared.global [%0], [%1], 16;\n" :: \
                 "r"((unsigned)__cvta_generic_to_shared(dst)), "l"(src))
#define CP_COMMIT() asm volatile("cp.async.commit_group;\n")
#define CP_WAIT3()  asm volatile("cp.async.wait_group 3;\n")

#define NKT (KC / 8)   // 288
#define NSTG 5
#define A_FLOATS (128 * 12)
#define B_FLOATS (8 * 136)
#define GEMM_SMEM (NSTG * (A_FLOATS + B_FLOATS) * 4)   // 52480 bytes

__global__ __launch_bounds__(128, 2) void gemm_kernel(float* __restrict__ out) {
    extern __shared__ float sm[];
    float (*As)[128][12] = (float(*)[128][12])sm;                    // [5][128][12]
    float (*Bs)[8][136]  = (float(*)[8][136])(sm + NSTG * A_FLOATS); // [5][8][136]

    const int t    = threadIdx.x;      // 0..127
    const int lane = t & 31, wid = t >> 5;
    const int warpM = wid >> 1, warpN = wid & 1;   // 2 x 2
    const int qid = lane >> 2, kq = lane & 3;
    const int bm = blockIdx.y * 128, bnn = blockIdx.x * 128;   // bx fastest = bn

    float acc[4][8][4];
#pragma unroll
    for (int a = 0; a < 4; a++)
#pragma unroll
        for (int b = 0; b < 8; b++)
#pragma unroll
            for (int c = 0; c < 4; c++) acc[a][b][c] = 0.0f;

    // staging indices: 2 A-chunks + 2 B-chunks of 16B per thread per stage
    const int am0 = t >> 1, aseg = (t & 1) * 4;
    const int am1 = (t + 128) >> 1;
    const int aseg1 = ((t + 128) & 1) * 4;
    const int bk0 = t >> 5, bn0 = (t & 31) * 4;
    const int bk1 = (t + 128) >> 5, bn1 = bn0;

    // prologue: issue stages 0..3 (4 groups in flight)
#pragma unroll
    for (int s = 0; s < 4; s++) {
        CP_ASYNC16(&As[s][am0][aseg],  g_cols + (size_t)(bm + am0) * KC + s * 8 + aseg);
        CP_ASYNC16(&As[s][am1][aseg1], g_cols + (size_t)(bm + am1) * KC + s * 8 + aseg1);
        CP_ASYNC16(&Bs[s][bk0][bn0],   g_wt + (size_t)(s * 8 + bk0) * OC + bnn + bn0);
        CP_ASYNC16(&Bs[s][bk1][bn1],   g_wt + (size_t)(s * 8 + bk1) * OC + bnn + bn1);
        CP_COMMIT();
    }

    int cur = 0;       // kt % 5
    int nsl = 4;       // (kt+4) % 5
    for (int kt = 0; kt < NKT; ++kt) {
        CP_WAIT3();            // stage kt resident
        __syncthreads();       // all warps done reading slot being overwritten

        // issue stage kt+4 into slot (kt+4)%5 (clamped at tail; the clamped
        // write targets the dead slot of stage kt-1 — never read again)
        {
            const int ks = (kt + 4 < NKT) ? (kt + 4) : (NKT - 1);
            CP_ASYNC16(&As[nsl][am0][aseg],  g_cols + (size_t)(bm + am0) * KC + ks * 8 + aseg);
            CP_ASYNC16(&As[nsl][am1][aseg1], g_cols + (size_t)(bm + am1) * KC + ks * 8 + aseg1);
            CP_ASYNC16(&Bs[nsl][bk0][bn0],   g_wt + (size_t)(ks * 8 + bk0) * OC + bnn + bn0);
            CP_ASYNC16(&Bs[nsl][bk1][bn1],   g_wt + (size_t)(ks * 8 + bk1) * OC + bnn + bn1);
            CP_COMMIT();
        }

        // B fragments: 8 n-subtiles of 8
        uint32_t bf[8][2];
#pragma unroll
        for (int ni = 0; ni < 8; ni++) {
            const int nb = warpN * 64 + ni * 8 + qid;
            bf[ni][0] = __float_as_uint(Bs[cur][kq][nb]);
            bf[ni][1] = __float_as_uint(Bs[cur][kq + 4][nb]);
        }
#pragma unroll
        for (int mi = 0; mi < 4; mi++) {
            const int mb = warpM * 64 + mi * 16 + qid;
            uint32_t a0 = __float_as_uint(As[cur][mb][kq]);
            uint32_t a1 = __float_as_uint(As[cur][mb + 8][kq]);
            uint32_t a2 = __float_as_uint(As[cur][mb][kq + 4]);
            uint32_t a3 = __float_as_uint(As[cur][mb + 8][kq + 4]);
#pragma unroll
            for (int ni = 0; ni < 8; ni++) {
                asm volatile(
                    "mma.sync.aligned.m16n8k8.row.col.f32.tf32.tf32.f32 "
                    "{%0,%1,%2,%3},{%4,%5,%6,%7},{%8,%9},{%0,%1,%2,%3};\n"
                    : "+f"(acc[mi][ni][0]), "+f"(acc[mi][ni][1]),
                      "+f"(acc[mi][ni][2]), "+f"(acc[mi][ni][3])
                    : "r"(a0), "r"(a1), "r"(a2), "r"(a3),
                      "r"(bf[ni][0]), "r"(bf[ni][1]));
            }
        }

        // advance mod-5 counters without division
        cur = (cur == NSTG - 1) ? 0 : cur + 1;
        nsl = (nsl == NSTG - 1) ? 0 : nsl + 1;
    }

    // epilogue: out[n][o][oh][ow]; m = n*4096 + p
#pragma unroll
    for (int mi = 0; mi < 4; mi++) {
#pragma unroll
        for (int h = 0; h < 2; h++) {
            const int m = bm + warpM * 64 + mi * 16 + qid + h * 8;
            const int nimg = m >> 12;
            const size_t base = ((size_t)nimg << 20) + (m & 4095);
#pragma unroll
            for (int ni = 0; ni < 8; ni++) {
                const int o = bnn + warpN * 64 + ni * 8 + kq * 2;
                out[base + (size_t)o * 4096]       = acc[mi][ni][h * 2 + 0];
                out[base + (size_t)(o + 1) * 4096] = acc[mi][ni][h * 2 + 1];
            }
        }
    }
}

// ---------------------------------------------------------------------------
extern "C" void kernel_launch(void* const* d_in, const int* in_sizes, int n_in,
                              void* d_out, int out_size) {
    const float* x      = (const float*)d_in[0];
    const float* offset = (const float*)d_in[1];
    const float* weight = (const float*)d_in[2];
    float* out = (float*)d_out;

    cudaFuncSetAttribute(gemm_kernel, cudaFuncAttributeMaxDynamicSharedMemorySize, GEMM_SMEM);

    transpose_x_kernel<<<dim3(128, 8, 8), dim3(32, 8)>>>(x);
    wt_kernel<<<KC, 256>>>(weight);
    gather_kernel<<<(MTOT * KK) / 8, 256>>>(offset);
    gemm_kernel<<<dim3(OC / 128, MTOT / 128), 128, GEMM_SMEM>>>(out);
}